// round 3
// baseline (speedup 1.0000x reference)
#include <cuda_runtime.h>
#include <cstdint>

// Problem dims (fixed by setup_inputs)
#define T_DIM 1024
#define B_DIM 32
#define D_DIM 768
#define N_DIM 64
#define PROJ_C 256          // 4*n : k | v | q | m
#define M_ROWS (T_DIM * B_DIM)

// Scratch: projection results [T, B, 256] fp32 (~33.5 MB) + per-row scalars
__device__ float  g_proj[(size_t)T_DIM * B_DIM * PROJ_C];
__device__ float4 g_scal[(size_t)T_DIM * B_DIM];   // {kk, mm, km, kq}

// ---------------------------------------------------------------------------
__device__ __forceinline__ float warp_sum32(float v) {
#pragma unroll
    for (int o = 16; o > 0; o >>= 1)
        v += __shfl_xor_sync(0xffffffffu, v, o);
    return v;
}

__device__ __forceinline__ float fast_sigmoid(float x) {
    return __fdividef(1.0f, 1.0f + __expf(-x));
}

// ---------------------------------------------------------------------------
// GEMM: proj[r, c] = sum_d x[r, d] * W[c, d]
//   Tile: 128 (M) x 64 (N), BK = 16, 256 threads, 8x4 per-thread microtile
// ---------------------------------------------------------------------------
__global__ void __launch_bounds__(256, 4)
gemm_kernel(const float* __restrict__ A, const float* __restrict__ W) {
    __shared__ float As[16][132];   // transposed, padded (strides keep 16B align)
    __shared__ float Bs[16][68];

    const int bm = blockIdx.x * 128;
    const int bn = blockIdx.y * 64;
    const int t  = threadIdx.x;
    const int tx = t & 15;
    const int ty = t >> 4;

    float acc[8][4];
#pragma unroll
    for (int x = 0; x < 8; ++x)
#pragma unroll
        for (int y = 0; y < 4; ++y) acc[x][y] = 0.0f;

    for (int k0 = 0; k0 < D_DIM; k0 += 16) {
#pragma unroll
        for (int p = 0; p < 2; ++p) {
            int f   = p * 256 + t;
            int row = f >> 2;
            int kq  = (f & 3) * 4;
            float4 v = *(const float4*)(A + (size_t)(bm + row) * D_DIM + k0 + kq);
            As[kq + 0][row] = v.x; As[kq + 1][row] = v.y;
            As[kq + 2][row] = v.z; As[kq + 3][row] = v.w;
        }
        {
            int row = t >> 2;
            int kq  = (t & 3) * 4;
            float4 v = *(const float4*)(W + (size_t)(bn + row) * D_DIM + k0 + kq);
            Bs[kq + 0][row] = v.x; Bs[kq + 1][row] = v.y;
            Bs[kq + 2][row] = v.z; Bs[kq + 3][row] = v.w;
        }
        __syncthreads();

#pragma unroll
        for (int kk = 0; kk < 16; ++kk) {
            float4 a0 = *(const float4*)&As[kk][ty * 8];
            float4 a1 = *(const float4*)&As[kk][ty * 8 + 4];
            float4 bv = *(const float4*)&Bs[kk][tx * 4];
            float a[8]  = {a0.x, a0.y, a0.z, a0.w, a1.x, a1.y, a1.z, a1.w};
            float bb[4] = {bv.x, bv.y, bv.z, bv.w};
#pragma unroll
            for (int x = 0; x < 8; ++x)
#pragma unroll
                for (int y = 0; y < 4; ++y)
                    acc[x][y] = fmaf(a[x], bb[y], acc[x][y]);
        }
        __syncthreads();
    }

#pragma unroll
    for (int x = 0; x < 8; ++x) {
        float4 v = make_float4(acc[x][0], acc[x][1], acc[x][2], acc[x][3]);
        *(float4*)(g_proj + (size_t)(bm + ty * 8 + x) * PROJ_C + bn + tx * 4) = v;
    }
}

// ---------------------------------------------------------------------------
// Normalize k (cols 0:64) and m (cols 192:256) per (t,b) row; also compute
// per-row scalars kk = <kn,kn>, mm = <mn,mn>, km = <kn,mn>, kq = <kn,q>.
// One warp per row, 32768 rows.
// ---------------------------------------------------------------------------
__global__ void norm_kernel() {
    const int w    = (blockIdx.x * blockDim.x + threadIdx.x) >> 5;
    const int lane = threadIdx.x & 31;
    if (w >= M_ROWS) return;
    float* p = g_proj + (size_t)w * PROJ_C;

    float k0 = p[lane],       k1 = p[lane + 32];
    float q0 = p[128 + lane], q1 = p[160 + lane];
    float m0 = p[192 + lane], m1 = p[224 + lane];

    // 4 interleaved butterfly reductions
    float sk  = fmaf(k0, k0, k1 * k1);
    float sm  = fmaf(m0, m0, m1 * m1);
    float skm = fmaf(k0, m0, k1 * m1);
    float skq = fmaf(k0, q0, k1 * q1);
#pragma unroll
    for (int o = 16; o > 0; o >>= 1) {
        float a = __shfl_xor_sync(0xffffffffu, sk,  o);
        float b = __shfl_xor_sync(0xffffffffu, sm,  o);
        float c = __shfl_xor_sync(0xffffffffu, skm, o);
        float d = __shfl_xor_sync(0xffffffffu, skq, o);
        sk += a; sm += b; skm += c; skq += d;
    }

    float ck = __fdividef(1.0f, sqrtf(sk) + 1e-6f);
    float cm = __fdividef(1.0f, sqrtf(sm) + 1e-6f);
    p[lane]       = k0 * ck;  p[lane + 32] = k1 * ck;
    p[192 + lane] = m0 * cm;  p[224 + lane] = m1 * cm;

    if (lane == 0) {
        float4 sc;
        sc.x = sk  * ck * ck;   // <kn,kn>
        sc.y = sm  * cm * cm;   // <mn,mn>
        sc.z = skm * ck * cm;   // <kn,mn>
        sc.w = skq * ck;        // <kn,q>
        g_scal[w] = sc;
    }
}

// ---------------------------------------------------------------------------
// Sequential scan with scalar-space RK4.
// Within a timestep every RK4 stage state lies in span{s,k} / span{g,m}:
//   cs = as*s + bs*k, cg = cc*g + dc*m  -> all gate/delta scalars follow
// closed scalar recursions. Full timestep: s <- A*s + B*k, g <- C*g + D*m.
// Layout: 8 lanes per row, 4 rows per warp (SIMD scalar chains across the
// four 8-lane groups). 512 warps total, fully independent.
// ---------------------------------------------------------------------------
__global__ void __launch_bounds__(128)
scan_kernel(const float* __restrict__ S0,
            const float* __restrict__ G0,
            const int*   __restrict__ ns_ptr,
            float* __restrict__ out) {
    const int w    = (blockIdx.x * blockDim.x + threadIdx.x) >> 5;
    const int lane = threadIdx.x & 31;
    const int b    = w >> 4;                 // 16 warps per batch
    const int grp  = (lane >> 3);            // row-group within warp (0..3)
    const int sub  = lane & 7;               // lane within 8-lane group
    const int i    = (w & 15) * 4 + grp;     // row index 0..63

    const int   ns  = ns_ptr ? *ns_ptr : 4;
    const float dt  = __fdividef(1.0f, (float)ns);
    const float h2  = 0.5f * dt;
    const float hd6 = dt * (1.0f / 6.0f);

    // State: 8 contiguous elems per lane
    const size_t sbase = ((size_t)b * N_DIM + i) * N_DIM + sub * 8;
    float s[8], g[8];
    {
        float4 a = *(const float4*)(S0 + sbase);
        float4 c = *(const float4*)(S0 + sbase + 4);
        s[0]=a.x; s[1]=a.y; s[2]=a.z; s[3]=a.w; s[4]=c.x; s[5]=c.y; s[6]=c.z; s[7]=c.w;
        float4 e = *(const float4*)(G0 + sbase);
        float4 f = *(const float4*)(G0 + sbase + 4);
        g[0]=e.x; g[1]=e.y; g[2]=e.z; g[3]=e.w; g[4]=f.x; g[5]=f.y; g[6]=f.z; g[7]=f.w;
    }

    // Preload t = 0 vectors + scalars
    float k[8], m[8], q[8], vi;
    float4 sc;
    {
        const float* pp = g_proj + ((size_t)b << 8);
        float4 a0 = *(const float4*)(pp + sub * 8);
        float4 a1 = *(const float4*)(pp + sub * 8 + 4);
        k[0]=a0.x; k[1]=a0.y; k[2]=a0.z; k[3]=a0.w; k[4]=a1.x; k[5]=a1.y; k[6]=a1.z; k[7]=a1.w;
        float4 q0 = *(const float4*)(pp + 128 + sub * 8);
        float4 q1 = *(const float4*)(pp + 128 + sub * 8 + 4);
        q[0]=q0.x; q[1]=q0.y; q[2]=q0.z; q[3]=q0.w; q[4]=q1.x; q[5]=q1.y; q[6]=q1.z; q[7]=q1.w;
        float4 m0 = *(const float4*)(pp + 192 + sub * 8);
        float4 m1 = *(const float4*)(pp + 192 + sub * 8 + 4);
        m[0]=m0.x; m[1]=m0.y; m[2]=m0.z; m[3]=m0.w; m[4]=m1.x; m[5]=m1.y; m[6]=m1.z; m[7]=m1.w;
        vi = pp[64 + i];
        sc = g_scal[b];
    }

    for (int t = 0; t < T_DIM; ++t) {
        // ---- 5 dot products over this 8-lane group (3-level butterfly) ----
        float pp_ = 0.f, rr = 0.f, uu = 0.f, ww = 0.f, zz = 0.f;
#pragma unroll
        for (int e = 0; e < 8; ++e) {
            pp_ = fmaf(s[e], k[e], pp_);
            rr  = fmaf(s[e], m[e], rr);
            uu  = fmaf(g[e], k[e], uu);
            ww  = fmaf(g[e], m[e], ww);
            zz  = fmaf(s[e], q[e], zz);
        }
#pragma unroll
        for (int o = 4; o > 0; o >>= 1) {
            pp_ += __shfl_xor_sync(0xffffffffu, pp_, o);
            rr  += __shfl_xor_sync(0xffffffffu, rr,  o);
            uu  += __shfl_xor_sync(0xffffffffu, uu,  o);
            ww  += __shfl_xor_sync(0xffffffffu, ww,  o);
            zz  += __shfl_xor_sync(0xffffffffu, zz,  o);
        }

        // ---- prefetch next timestep (overlaps the scalar chain) ----
        float nk[8], nm[8], nq[8], nvi = 0.f;
        float4 nsc = sc;
        if (t + 1 < T_DIM) {
            const float* np = g_proj + ((size_t)((t + 1) * B_DIM + b) << 8);
            float4 a0 = *(const float4*)(np + sub * 8);
            float4 a1 = *(const float4*)(np + sub * 8 + 4);
            nk[0]=a0.x; nk[1]=a0.y; nk[2]=a0.z; nk[3]=a0.w; nk[4]=a1.x; nk[5]=a1.y; nk[6]=a1.z; nk[7]=a1.w;
            float4 q0 = *(const float4*)(np + 128 + sub * 8);
            float4 q1 = *(const float4*)(np + 128 + sub * 8 + 4);
            nq[0]=q0.x; nq[1]=q0.y; nq[2]=q0.z; nq[3]=q0.w; nq[4]=q1.x; nq[5]=q1.y; nq[6]=q1.z; nq[7]=q1.w;
            float4 m0 = *(const float4*)(np + 192 + sub * 8);
            float4 m1 = *(const float4*)(np + 192 + sub * 8 + 4);
            nm[0]=m0.x; nm[1]=m0.y; nm[2]=m0.z; nm[3]=m0.w; nm[4]=m1.x; nm[5]=m1.y; nm[6]=m1.z; nm[7]=m1.w;
            nvi = np[64 + i];
            nsc = g_scal[(t + 1) * B_DIM + b];
        } else {
#pragma unroll
            for (int e = 0; e < 8; ++e) { nk[e]=0.f; nm[e]=0.f; nq[e]=0.f; }
        }

        const float kk = sc.x, mm = sc.y, km = sc.z, kq = sc.w;

        // ---- scalar-space RK4: ns substeps x 4 stages ----
        float A = 1.f, Bc = 0.f, Cc = 1.f, Dc = 0.f;   // s<-A s + Bc k ; g<-Cc g + Dc m
        float p = pp_, r = rr, u = uu, wv = ww;
        for (int ssi = 0; ssi < ns; ++ssi) {
            float aSa = 0.f, aSb = 0.f, aGc = 0.f, aGd = 0.f;
            float as = 1.f, bs = 0.f, cc = 1.f, dc = 0.f;
#pragma unroll
            for (int st = 0; st < 4; ++st) {
                float p_st = fmaf(bs, kk, as * p);
                float r_st = fmaf(bs, km, as * r);
                float u_st = fmaf(dc, km, cc * u);
                float w_st = fmaf(dc, mm, cc * wv);
                float dSs  = vi - p_st;
                float dGs  = dSs - w_st;
                float aa   = fast_sigmoid(u_st) - 1.0f;
                float bb   = fast_sigmoid(r_st) - 1.0f;
                float dSa  = aa * as;
                float dSb  = fmaf(aa, bs, dSs);
                float dGc  = bb * cc;
                float dGd  = fmaf(bb, dc, dGs);
                float wgt  = (st == 1 || st == 2) ? 2.0f : 1.0f;
                aSa = fmaf(wgt, dSa, aSa);
                aSb = fmaf(wgt, dSb, aSb);
                aGc = fmaf(wgt, dGc, aGc);
                aGd = fmaf(wgt, dGd, aGd);
                if (st < 3) {
                    float c = (st == 2) ? dt : h2;
                    as = fmaf(c, dSa, 1.0f);
                    bs = c * dSb;
                    cc = fmaf(c, dGc, 1.0f);
                    dc = c * dGd;
                }
            }
            float a_s = fmaf(hd6, aSa, 1.0f), b_s = hd6 * aSb;
            float c_g = fmaf(hd6, aGc, 1.0f), d_g = hd6 * aGd;
            A  = a_s * A;  Bc = fmaf(a_s, Bc, b_s);
            Cc = c_g * Cc; Dc = fmaf(c_g, Dc, d_g);
            p  = fmaf(b_s, kk, a_s * p);
            r  = fmaf(b_s, km, a_s * r);
            u  = fmaf(d_g, km, c_g * u);
            wv = fmaf(d_g, mm, c_g * wv);
        }

        // ---- output: z = <s_end, q> = A*<s_prev,q> + B*<k,q> ----
        float z = fmaf(Bc, kq, A * zz);
        if (sub == 0) {
            out[((size_t)t * B_DIM + b) * N_DIM + i] = z * z * fast_sigmoid(z);
        }

        // ---- rank-1 state update ----
#pragma unroll
        for (int e = 0; e < 8; ++e) {
            s[e] = fmaf(A,  s[e], Bc * k[e]);
            g[e] = fmaf(Cc, g[e], Dc * m[e]);
        }

        // swap in prefetched vectors
#pragma unroll
        for (int e = 0; e < 8; ++e) { k[e] = nk[e]; m[e] = nm[e]; q[e] = nq[e]; }
        vi = nvi; sc = nsc;
    }

    // Final S, G: out layout = outputs [T*B*N] | S [B,N,N] | G [B,N,N]
    float* Sout = out + (size_t)T_DIM * B_DIM * N_DIM;
    float* Gout = Sout + (size_t)B_DIM * N_DIM * N_DIM;
    *(float4*)(Sout + sbase)     = make_float4(s[0], s[1], s[2], s[3]);
    *(float4*)(Sout + sbase + 4) = make_float4(s[4], s[5], s[6], s[7]);
    *(float4*)(Gout + sbase)     = make_float4(g[0], g[1], g[2], g[3]);
    *(float4*)(Gout + sbase + 4) = make_float4(g[4], g[5], g[6], g[7]);
}

// ---------------------------------------------------------------------------
extern "C" void kernel_launch(void* const* d_in, const int* in_sizes, int n_in,
                              void* d_out, int out_size) {
    const float* x  = (const float*)d_in[0];   // [T, B, 768]
    const float* S0 = (const float*)d_in[1];   // [B, 64, 64]
    const float* G0 = (const float*)d_in[2];   // [B, 64, 64]
    const float* W  = (const float*)d_in[3];   // [256, 768]
    const int*   ns = (n_in > 4) ? (const int*)d_in[4] : nullptr;
    float* out = (float*)d_out;

    dim3 ggrid(M_ROWS / 128, PROJ_C / 64);
    gemm_kernel<<<ggrid, 256>>>(x, W);

    norm_kernel<<<(M_ROWS * 32) / 256, 256>>>();

    // 512 warps: 4 rows per warp, 8 lanes per row
    scan_kernel<<<(B_DIM * (N_DIM / 4) * 32) / 128, 128>>>(S0, G0, ns, out);
}

// round 4
// speedup vs baseline: 1.0000x; 1.0000x over previous
#include <cuda_runtime.h>
#include <cstdint>

// Problem dims (fixed by setup_inputs)
#define T_DIM 1024
#define B_DIM 32
#define D_DIM 768
#define N_DIM 64
#define PROJ_C 256          // 4*n : k | v | q | m
#define M_ROWS (T_DIM * B_DIM)

// Scratch: projection results [T, B, 256] fp32 (~33.5 MB) + per-row scalars
__device__ float  g_proj[(size_t)T_DIM * B_DIM * PROJ_C];
__device__ float4 g_scal[(size_t)T_DIM * B_DIM];   // {kk, mm, km, kq}

// ---------------------------------------------------------------------------
__device__ __forceinline__ float warp_sum32(float v) {
#pragma unroll
    for (int o = 16; o > 0; o >>= 1)
        v += __shfl_xor_sync(0xffffffffu, v, o);
    return v;
}

__device__ __forceinline__ float fast_sigmoid(float x) {
    return __fdividef(1.0f, 1.0f + __expf(-x));
}

// ---------------------------------------------------------------------------
// GEMM: proj[r, c] = sum_d x[r, d] * W[c, d]
//   Tile: 128 (M) x 64 (N), BK = 16, 256 threads, 8x4 per-thread microtile
// ---------------------------------------------------------------------------
__global__ void __launch_bounds__(256, 4)
gemm_kernel(const float* __restrict__ A, const float* __restrict__ W) {
    __shared__ float As[16][132];   // transposed, padded (strides keep 16B align)
    __shared__ float Bs[16][68];

    const int bm = blockIdx.x * 128;
    const int bn = blockIdx.y * 64;
    const int t  = threadIdx.x;
    const int tx = t & 15;
    const int ty = t >> 4;

    float acc[8][4];
#pragma unroll
    for (int x = 0; x < 8; ++x)
#pragma unroll
        for (int y = 0; y < 4; ++y) acc[x][y] = 0.0f;

    for (int k0 = 0; k0 < D_DIM; k0 += 16) {
#pragma unroll
        for (int p = 0; p < 2; ++p) {
            int f   = p * 256 + t;
            int row = f >> 2;
            int kq  = (f & 3) * 4;
            float4 v = *(const float4*)(A + (size_t)(bm + row) * D_DIM + k0 + kq);
            As[kq + 0][row] = v.x; As[kq + 1][row] = v.y;
            As[kq + 2][row] = v.z; As[kq + 3][row] = v.w;
        }
        {
            int row = t >> 2;
            int kq  = (t & 3) * 4;
            float4 v = *(const float4*)(W + (size_t)(bn + row) * D_DIM + k0 + kq);
            Bs[kq + 0][row] = v.x; Bs[kq + 1][row] = v.y;
            Bs[kq + 2][row] = v.z; Bs[kq + 3][row] = v.w;
        }
        __syncthreads();

#pragma unroll
        for (int kk = 0; kk < 16; ++kk) {
            float4 a0 = *(const float4*)&As[kk][ty * 8];
            float4 a1 = *(const float4*)&As[kk][ty * 8 + 4];
            float4 bv = *(const float4*)&Bs[kk][tx * 4];
            float a[8]  = {a0.x, a0.y, a0.z, a0.w, a1.x, a1.y, a1.z, a1.w};
            float bb[4] = {bv.x, bv.y, bv.z, bv.w};
#pragma unroll
            for (int x = 0; x < 8; ++x)
#pragma unroll
                for (int y = 0; y < 4; ++y)
                    acc[x][y] = fmaf(a[x], bb[y], acc[x][y]);
        }
        __syncthreads();
    }

#pragma unroll
    for (int x = 0; x < 8; ++x) {
        float4 v = make_float4(acc[x][0], acc[x][1], acc[x][2], acc[x][3]);
        *(float4*)(g_proj + (size_t)(bm + ty * 8 + x) * PROJ_C + bn + tx * 4) = v;
    }
}

// ---------------------------------------------------------------------------
// Normalize k (cols 0:64) and m (cols 192:256) per (t,b) row; also compute
// per-row scalars kk = <kn,kn>, mm = <mn,mn>, km = <kn,mn>, kq = <kn,q>.
// One warp per row, 32768 rows.
// ---------------------------------------------------------------------------
__global__ void norm_kernel() {
    const int w    = (blockIdx.x * blockDim.x + threadIdx.x) >> 5;
    const int lane = threadIdx.x & 31;
    if (w >= M_ROWS) return;
    float* p = g_proj + (size_t)w * PROJ_C;

    float k0 = p[lane],       k1 = p[lane + 32];
    float q0 = p[128 + lane], q1 = p[160 + lane];
    float m0 = p[192 + lane], m1 = p[224 + lane];

    // 4 interleaved butterfly reductions
    float sk  = fmaf(k0, k0, k1 * k1);
    float sm  = fmaf(m0, m0, m1 * m1);
    float skm = fmaf(k0, m0, k1 * m1);
    float skq = fmaf(k0, q0, k1 * q1);
#pragma unroll
    for (int o = 16; o > 0; o >>= 1) {
        float a = __shfl_xor_sync(0xffffffffu, sk,  o);
        float b = __shfl_xor_sync(0xffffffffu, sm,  o);
        float c = __shfl_xor_sync(0xffffffffu, skm, o);
        float d = __shfl_xor_sync(0xffffffffu, skq, o);
        sk += a; sm += b; skm += c; skq += d;
    }

    float ck = __fdividef(1.0f, sqrtf(sk) + 1e-6f);
    float cm = __fdividef(1.0f, sqrtf(sm) + 1e-6f);
    p[lane]       = k0 * ck;  p[lane + 32] = k1 * ck;
    p[192 + lane] = m0 * cm;  p[224 + lane] = m1 * cm;

    if (lane == 0) {
        float4 sc;
        sc.x = sk  * ck * ck;   // <kn,kn>
        sc.y = sm  * cm * cm;   // <mn,mn>
        sc.z = skm * ck * cm;   // <kn,mn>
        sc.w = skq * ck;        // <kn,q>
        g_scal[w] = sc;
    }
}

// ---------------------------------------------------------------------------
// Sequential scan with scalar-space RK4.
// Within a timestep every RK4 stage state lies in span{s,k} / span{g,m}:
//   cs = as*s + bs*k, cg = cc*g + dc*m  -> all gate/delta scalars follow
// closed scalar recursions. Full timestep: s <- A*s + B*k, g <- C*g + D*m.
// Layout: 8 lanes per row, 4 rows per warp (SIMD scalar chains across the
// four 8-lane groups). 512 warps total, fully independent.
// ---------------------------------------------------------------------------
__global__ void __launch_bounds__(128)
scan_kernel(const float* __restrict__ S0,
            const float* __restrict__ G0,
            const int*   __restrict__ ns_ptr,
            float* __restrict__ out) {
    const int w    = (blockIdx.x * blockDim.x + threadIdx.x) >> 5;
    const int lane = threadIdx.x & 31;
    const int b    = w >> 4;                 // 16 warps per batch
    const int grp  = (lane >> 3);            // row-group within warp (0..3)
    const int sub  = lane & 7;               // lane within 8-lane group
    const int i    = (w & 15) * 4 + grp;     // row index 0..63

    const int   ns  = ns_ptr ? *ns_ptr : 4;
    const float dt  = __fdividef(1.0f, (float)ns);
    const float h2  = 0.5f * dt;
    const float hd6 = dt * (1.0f / 6.0f);

    // State: 8 contiguous elems per lane
    const size_t sbase = ((size_t)b * N_DIM + i) * N_DIM + sub * 8;
    float s[8], g[8];
    {
        float4 a = *(const float4*)(S0 + sbase);
        float4 c = *(const float4*)(S0 + sbase + 4);
        s[0]=a.x; s[1]=a.y; s[2]=a.z; s[3]=a.w; s[4]=c.x; s[5]=c.y; s[6]=c.z; s[7]=c.w;
        float4 e = *(const float4*)(G0 + sbase);
        float4 f = *(const float4*)(G0 + sbase + 4);
        g[0]=e.x; g[1]=e.y; g[2]=e.z; g[3]=e.w; g[4]=f.x; g[5]=f.y; g[6]=f.z; g[7]=f.w;
    }

    // Preload t = 0 vectors + scalars
    float k[8], m[8], q[8], vi;
    float4 sc;
    {
        const float* pp = g_proj + ((size_t)b << 8);
        float4 a0 = *(const float4*)(pp + sub * 8);
        float4 a1 = *(const float4*)(pp + sub * 8 + 4);
        k[0]=a0.x; k[1]=a0.y; k[2]=a0.z; k[3]=a0.w; k[4]=a1.x; k[5]=a1.y; k[6]=a1.z; k[7]=a1.w;
        float4 q0 = *(const float4*)(pp + 128 + sub * 8);
        float4 q1 = *(const float4*)(pp + 128 + sub * 8 + 4);
        q[0]=q0.x; q[1]=q0.y; q[2]=q0.z; q[3]=q0.w; q[4]=q1.x; q[5]=q1.y; q[6]=q1.z; q[7]=q1.w;
        float4 m0 = *(const float4*)(pp + 192 + sub * 8);
        float4 m1 = *(const float4*)(pp + 192 + sub * 8 + 4);
        m[0]=m0.x; m[1]=m0.y; m[2]=m0.z; m[3]=m0.w; m[4]=m1.x; m[5]=m1.y; m[6]=m1.z; m[7]=m1.w;
        vi = pp[64 + i];
        sc = g_scal[b];
    }

    for (int t = 0; t < T_DIM; ++t) {
        // ---- 5 dot products over this 8-lane group (3-level butterfly) ----
        float pp_ = 0.f, rr = 0.f, uu = 0.f, ww = 0.f, zz = 0.f;
#pragma unroll
        for (int e = 0; e < 8; ++e) {
            pp_ = fmaf(s[e], k[e], pp_);
            rr  = fmaf(s[e], m[e], rr);
            uu  = fmaf(g[e], k[e], uu);
            ww  = fmaf(g[e], m[e], ww);
            zz  = fmaf(s[e], q[e], zz);
        }
#pragma unroll
        for (int o = 4; o > 0; o >>= 1) {
            pp_ += __shfl_xor_sync(0xffffffffu, pp_, o);
            rr  += __shfl_xor_sync(0xffffffffu, rr,  o);
            uu  += __shfl_xor_sync(0xffffffffu, uu,  o);
            ww  += __shfl_xor_sync(0xffffffffu, ww,  o);
            zz  += __shfl_xor_sync(0xffffffffu, zz,  o);
        }

        // ---- prefetch next timestep (overlaps the scalar chain) ----
        float nk[8], nm[8], nq[8], nvi = 0.f;
        float4 nsc = sc;
        if (t + 1 < T_DIM) {
            const float* np = g_proj + ((size_t)((t + 1) * B_DIM + b) << 8);
            float4 a0 = *(const float4*)(np + sub * 8);
            float4 a1 = *(const float4*)(np + sub * 8 + 4);
            nk[0]=a0.x; nk[1]=a0.y; nk[2]=a0.z; nk[3]=a0.w; nk[4]=a1.x; nk[5]=a1.y; nk[6]=a1.z; nk[7]=a1.w;
            float4 q0 = *(const float4*)(np + 128 + sub * 8);
            float4 q1 = *(const float4*)(np + 128 + sub * 8 + 4);
            nq[0]=q0.x; nq[1]=q0.y; nq[2]=q0.z; nq[3]=q0.w; nq[4]=q1.x; nq[5]=q1.y; nq[6]=q1.z; nq[7]=q1.w;
            float4 m0 = *(const float4*)(np + 192 + sub * 8);
            float4 m1 = *(const float4*)(np + 192 + sub * 8 + 4);
            nm[0]=m0.x; nm[1]=m0.y; nm[2]=m0.z; nm[3]=m0.w; nm[4]=m1.x; nm[5]=m1.y; nm[6]=m1.z; nm[7]=m1.w;
            nvi = np[64 + i];
            nsc = g_scal[(t + 1) * B_DIM + b];
        } else {
#pragma unroll
            for (int e = 0; e < 8; ++e) { nk[e]=0.f; nm[e]=0.f; nq[e]=0.f; }
        }

        const float kk = sc.x, mm = sc.y, km = sc.z, kq = sc.w;

        // ---- scalar-space RK4: ns substeps x 4 stages ----
        float A = 1.f, Bc = 0.f, Cc = 1.f, Dc = 0.f;   // s<-A s + Bc k ; g<-Cc g + Dc m
        float p = pp_, r = rr, u = uu, wv = ww;
        for (int ssi = 0; ssi < ns; ++ssi) {
            float aSa = 0.f, aSb = 0.f, aGc = 0.f, aGd = 0.f;
            float as = 1.f, bs = 0.f, cc = 1.f, dc = 0.f;
#pragma unroll
            for (int st = 0; st < 4; ++st) {
                float p_st = fmaf(bs, kk, as * p);
                float r_st = fmaf(bs, km, as * r);
                float u_st = fmaf(dc, km, cc * u);
                float w_st = fmaf(dc, mm, cc * wv);
                float dSs  = vi - p_st;
                float dGs  = dSs - w_st;
                float aa   = fast_sigmoid(u_st) - 1.0f;
                float bb   = fast_sigmoid(r_st) - 1.0f;
                float dSa  = aa * as;
                float dSb  = fmaf(aa, bs, dSs);
                float dGc  = bb * cc;
                float dGd  = fmaf(bb, dc, dGs);
                float wgt  = (st == 1 || st == 2) ? 2.0f : 1.0f;
                aSa = fmaf(wgt, dSa, aSa);
                aSb = fmaf(wgt, dSb, aSb);
                aGc = fmaf(wgt, dGc, aGc);
                aGd = fmaf(wgt, dGd, aGd);
                if (st < 3) {
                    float c = (st == 2) ? dt : h2;
                    as = fmaf(c, dSa, 1.0f);
                    bs = c * dSb;
                    cc = fmaf(c, dGc, 1.0f);
                    dc = c * dGd;
                }
            }
            float a_s = fmaf(hd6, aSa, 1.0f), b_s = hd6 * aSb;
            float c_g = fmaf(hd6, aGc, 1.0f), d_g = hd6 * aGd;
            A  = a_s * A;  Bc = fmaf(a_s, Bc, b_s);
            Cc = c_g * Cc; Dc = fmaf(c_g, Dc, d_g);
            p  = fmaf(b_s, kk, a_s * p);
            r  = fmaf(b_s, km, a_s * r);
            u  = fmaf(d_g, km, c_g * u);
            wv = fmaf(d_g, mm, c_g * wv);
        }

        // ---- output: z = <s_end, q> = A*<s_prev,q> + B*<k,q> ----
        float z = fmaf(Bc, kq, A * zz);
        if (sub == 0) {
            out[((size_t)t * B_DIM + b) * N_DIM + i] = z * z * fast_sigmoid(z);
        }

        // ---- rank-1 state update ----
#pragma unroll
        for (int e = 0; e < 8; ++e) {
            s[e] = fmaf(A,  s[e], Bc * k[e]);
            g[e] = fmaf(Cc, g[e], Dc * m[e]);
        }

        // swap in prefetched vectors
#pragma unroll
        for (int e = 0; e < 8; ++e) { k[e] = nk[e]; m[e] = nm[e]; q[e] = nq[e]; }
        vi = nvi; sc = nsc;
    }

    // Final S, G: out layout = outputs [T*B*N] | S [B,N,N] | G [B,N,N]
    float* Sout = out + (size_t)T_DIM * B_DIM * N_DIM;
    float* Gout = Sout + (size_t)B_DIM * N_DIM * N_DIM;
    *(float4*)(Sout + sbase)     = make_float4(s[0], s[1], s[2], s[3]);
    *(float4*)(Sout + sbase + 4) = make_float4(s[4], s[5], s[6], s[7]);
    *(float4*)(Gout + sbase)     = make_float4(g[0], g[1], g[2], g[3]);
    *(float4*)(Gout + sbase + 4) = make_float4(g[4], g[5], g[6], g[7]);
}

// ---------------------------------------------------------------------------
extern "C" void kernel_launch(void* const* d_in, const int* in_sizes, int n_in,
                              void* d_out, int out_size) {
    const float* x  = (const float*)d_in[0];   // [T, B, 768]
    const float* S0 = (const float*)d_in[1];   // [B, 64, 64]
    const float* G0 = (const float*)d_in[2];   // [B, 64, 64]
    const float* W  = (const float*)d_in[3];   // [256, 768]
    const int*   ns = (n_in > 4) ? (const int*)d_in[4] : nullptr;
    float* out = (float*)d_out;

    dim3 ggrid(M_ROWS / 128, PROJ_C / 64);
    gemm_kernel<<<ggrid, 256>>>(x, W);

    norm_kernel<<<(M_ROWS * 32) / 256, 256>>>();

    // 512 warps: 4 rows per warp, 8 lanes per row
    scan_kernel<<<(B_DIM * (N_DIM / 4) * 32) / 128, 128>>>(S0, G0, ns, out);
}